// round 1
// baseline (speedup 1.0000x reference)
#include <cuda_runtime.h>
#include <cstdint>
#include <math_constants.h>

#define TOKENS   32768
#define DIM      2048
#define NE       64
#define TOPK     6

#define BM       128      // tokens per block
#define BK       16       // k-chunk
#define THREADS  128

// packed f32x2 fma: d = a*b + c on two fp32 lanes in a 64-bit register pair
__device__ __forceinline__ unsigned long long fma2(unsigned long long a,
                                                   unsigned long long b,
                                                   unsigned long long c) {
    unsigned long long d;
    asm("fma.rn.f32x2 %0, %1, %2, %3;" : "=l"(d) : "l"(a), "l"(b), "l"(c));
    return d;
}

__global__ __launch_bounds__(THREADS)
void gate_kernel(const float* __restrict__ x,
                 const float* __restrict__ w,
                 const float* __restrict__ bias,
                 float* __restrict__ out)
{
    // smem overlay:
    //   mainloop: As = [BK][BM] floats (8KB) | Ws = [BK][NE] float2 dup pairs (8KB)
    //   epilogue: sLog = [BM][65] floats (33280B) overlays both
    //   sBias at byte 33280 (untouched by either)
    __shared__ __align__(16) unsigned char smem_raw[33280 + NE * 4];
    float*  As    = reinterpret_cast<float*>(smem_raw);                 // [BK][BM]
    float2* Ws    = reinterpret_cast<float2*>(smem_raw + 8192);         // [BK][NE]
    float*  sLog  = reinterpret_cast<float*>(smem_raw);                 // [BM][65]
    float*  sBias = reinterpret_cast<float*>(smem_raw + 33280);         // [NE]

    const int tid = threadIdx.x;
    const int tx  = tid & 7;    // expert-group (8 experts each)
    const int ty  = tid >> 3;   // token-group  (8 tokens each)
    const int block_m = blockIdx.x * BM;

    if (tid < NE) sBias[tid] = bias[tid];

    const float* xg = x + (size_t)block_m * DIM;

    // prefetch registers
    float4 xr[4];
    float4 wr[2];

    // acc[token_pair 0..3][expert 0..7], each a packed f32x2 (2 adjacent tokens)
    unsigned long long acc[4][8];
    #pragma unroll
    for (int a = 0; a < 4; a++)
        #pragma unroll
        for (int b = 0; b < 8; b++) acc[a][b] = 0ull;

    // ---- prefetch chunk 0 ----
    #pragma unroll
    for (int i = 0; i < 4; i++) {
        int li = i * THREADS + tid; int tok = li >> 2, dq = li & 3;
        xr[i] = *reinterpret_cast<const float4*>(xg + (size_t)tok * DIM + dq * 4);
    }
    #pragma unroll
    for (int i = 0; i < 2; i++) {
        int li = i * THREADS + tid; int e = li >> 2, dq = li & 3;
        wr[i] = *reinterpret_cast<const float4*>(w + (size_t)e * DIM + dq * 4);
    }

    for (int k0 = 0; k0 < DIM; k0 += BK) {
        // ---- store prefetched regs to smem (x transposed, w value-duplicated) ----
        #pragma unroll
        for (int i = 0; i < 4; i++) {
            int li = i * THREADS + tid; int tok = li >> 2, dq = li & 3;
            As[(dq * 4 + 0) * BM + tok] = xr[i].x;
            As[(dq * 4 + 1) * BM + tok] = xr[i].y;
            As[(dq * 4 + 2) * BM + tok] = xr[i].z;
            As[(dq * 4 + 3) * BM + tok] = xr[i].w;
        }
        #pragma unroll
        for (int i = 0; i < 2; i++) {
            int li = i * THREADS + tid; int e = li >> 2, dq = li & 3;
            Ws[(dq * 4 + 0) * NE + e] = make_float2(wr[i].x, wr[i].x);
            Ws[(dq * 4 + 1) * NE + e] = make_float2(wr[i].y, wr[i].y);
            Ws[(dq * 4 + 2) * NE + e] = make_float2(wr[i].z, wr[i].z);
            Ws[(dq * 4 + 3) * NE + e] = make_float2(wr[i].w, wr[i].w);
        }
        __syncthreads();

        // ---- prefetch next chunk while computing this one ----
        int kn = k0 + BK;
        if (kn < DIM) {
            #pragma unroll
            for (int i = 0; i < 4; i++) {
                int li = i * THREADS + tid; int tok = li >> 2, dq = li & 3;
                xr[i] = *reinterpret_cast<const float4*>(xg + (size_t)tok * DIM + kn + dq * 4);
            }
            #pragma unroll
            for (int i = 0; i < 2; i++) {
                int li = i * THREADS + tid; int e = li >> 2, dq = li & 3;
                wr[i] = *reinterpret_cast<const float4*>(w + (size_t)e * DIM + kn + dq * 4);
            }
        }

        // ---- compute: 16 k-steps x (4 token-pairs x 8 experts) f32x2 FMAs ----
        #pragma unroll
        for (int kk = 0; kk < BK; kk++) {
            ulonglong2 x01 = *reinterpret_cast<const ulonglong2*>(&As[kk * BM + ty * 8]);
            ulonglong2 x23 = *reinterpret_cast<const ulonglong2*>(&As[kk * BM + ty * 8 + 4]);
            unsigned long long xp[4] = { x01.x, x01.y, x23.x, x23.y };
            const ulonglong2* wrow = reinterpret_cast<const ulonglong2*>(&Ws[kk * NE + tx * 8]);
            ulonglong2 w01 = wrow[0], w23 = wrow[1], w45 = wrow[2], w67 = wrow[3];
            unsigned long long wv[8] = { w01.x, w01.y, w23.x, w23.y,
                                         w45.x, w45.y, w67.x, w67.y };
            #pragma unroll
            for (int tp = 0; tp < 4; tp++)
                #pragma unroll
                for (int j = 0; j < 8; j++)
                    acc[tp][j] = fma2(xp[tp], wv[j], acc[tp][j]);
        }
        __syncthreads();
    }

    // ---- dump logits to shared (row stride 65 -> conflict-free per-token rows) ----
    #pragma unroll
    for (int tp = 0; tp < 4; tp++) {
        #pragma unroll
        for (int j = 0; j < 8; j++) {
            uint2 u; 
            asm("mov.b64 {%0,%1}, %2;" : "=r"(u.x), "=r"(u.y) : "l"(acc[tp][j]));
            int e = tx * 8 + j;
            sLog[(ty * 8 + tp * 2 + 0) * 65 + e] = __uint_as_float(u.x);
            sLog[(ty * 8 + tp * 2 + 1) * 65 + e] = __uint_as_float(u.y);
        }
    }
    __syncthreads();

    // ---- fused epilogue: 1 thread = 1 token. softmax, +bias select, top-6 ----
    {
        float* row = sLog + tid * 65;

        float m = row[0];
        #pragma unroll
        for (int e = 1; e < NE; e++) m = fmaxf(m, row[e]);

        float s = 0.f;
        #pragma unroll
        for (int e = 0; e < NE; e++) { float ex = __expf(row[e] - m); row[e] = ex; s += ex; }
        float inv = 1.0f / s;
        #pragma unroll
        for (int e = 0; e < NE; e++) row[e] *= inv;   // row = original softmax scores

        const int t = block_m + tid;
        float* outw = out + (size_t)t * TOPK;
        float* outi = out + (size_t)TOKENS * TOPK + (size_t)t * TOPK;

        #pragma unroll
        for (int k = 0; k < TOPK; k++) {
            float best = -CUDART_INF_F; int bi = 0;
            #pragma unroll
            for (int e = 0; e < NE; e++) {
                float b = row[e] + sBias[e];   // bias affects selection only
                if (b > best) { best = b; bi = e; }
            }
            outw[k] = row[bi];                 // ROUTE_SCALE == 1.0
            outi[k] = (float)bi;
            row[bi] = -CUDART_INF_F;           // exclude (-inf + bias = -inf)
        }
    }
}

extern "C" void kernel_launch(void* const* d_in, const int* in_sizes, int n_in,
                              void* d_out, int out_size)
{
    const float* x    = (const float*)d_in[0];
    const float* w    = (const float*)d_in[1];
    const float* bias = (const float*)d_in[2];
    float* out = (float*)d_out;
    gate_kernel<<<TOKENS / BM, THREADS>>>(x, w, bias, out);
}

// round 2
// speedup vs baseline: 1.8819x; 1.8819x over previous
#include <cuda_runtime.h>
#include <cstdint>
#include <math_constants.h>

#define TOKENS   32768
#define DIM      2048
#define NE       64
#define TOPK     6

#define BM       128      // tokens per block
#define BK       16       // k-chunk
#define THREADS  256

#define ASTR     132      // As row stride (floats): 528B, 16B-aligned, kills conflicts
#define WSTR     68       // Ws row stride (floats): 272B, 16B-aligned
#define LSTR     66       // logits row stride (floats): 264B, 8B-aligned

typedef unsigned long long ull;

// packed f32x2 fma: two fp32 FMAs in one instruction
__device__ __forceinline__ ull fma2(ull a, ull b, ull c) {
    ull d;
    asm("fma.rn.f32x2 %0, %1, %2, %3;" : "=l"(d) : "l"(a), "l"(b), "l"(c));
    return d;
}

// duplicate a scalar into both lanes of an f32x2 (2 MOVs on the idle alu pipe)
__device__ __forceinline__ ull dup2(float v) {
    ull d;
    asm("mov.b64 %0, {%1, %1};" : "=l"(d) : "f"(v));
    return d;
}

__global__ __launch_bounds__(THREADS)
void gate_kernel(const float* __restrict__ x,
                 const float* __restrict__ w,
                 const float* __restrict__ bias,
                 float* __restrict__ out)
{
    // smem overlay:
    //   mainloop: As [BK][ASTR] (8448B) | Ws [BK][WSTR] (4352B)   = 12800B
    //   epilogue: sLog [BM][LSTR] (33792B) overlays both
    //   sBias after sLog (untouched by mainloop)
    __shared__ __align__(16) unsigned char smem_raw[BM * LSTR * 4 + NE * 4];
    float* As    = reinterpret_cast<float*>(smem_raw);                   // [BK][ASTR]
    float* Ws    = reinterpret_cast<float*>(smem_raw + BK * ASTR * 4);   // [BK][WSTR]
    float* sLog  = reinterpret_cast<float*>(smem_raw);                   // [BM][LSTR]
    float* sBias = reinterpret_cast<float*>(smem_raw + BM * LSTR * 4);   // [NE]

    const int tid = threadIdx.x;
    const int tx  = tid & 7;    // expert octet: experts tx*8 .. tx*8+7 (4 f32x2 pairs)
    const int ty  = tid >> 3;   // token quad:  tokens ty*4 .. ty*4+3
    const int block_m = blockIdx.x * BM;

    if (tid < NE) sBias[tid] = bias[tid];

    const float* xg = x + (size_t)block_m * DIM;

    // register prefetch buffers
    float4 xr[2];
    float4 wr;

    // acc[token 0..3][expert-pair 0..3]: experts packed as f32x2
    ull acc[4][4];
    #pragma unroll
    for (int t = 0; t < 4; t++)
        #pragma unroll
        for (int ep = 0; ep < 4; ep++) acc[t][ep] = 0ull;

    // ---- prefetch chunk 0 ----
    #pragma unroll
    for (int i = 0; i < 2; i++) {
        int li = i * THREADS + tid; int tok = li >> 2, dq = li & 3;
        xr[i] = *reinterpret_cast<const float4*>(xg + (size_t)tok * DIM + dq * 4);
    }
    {
        int e = tid >> 2, dq = tid & 3;
        wr = *reinterpret_cast<const float4*>(w + (size_t)e * DIM + dq * 4);
    }

    for (int k0 = 0; k0 < DIM; k0 += BK) {
        // ---- store prefetched regs to smem (x transposed, W plain) ----
        #pragma unroll
        for (int i = 0; i < 2; i++) {
            int li = i * THREADS + tid; int tok = li >> 2, dq = li & 3;
            As[(dq * 4 + 0) * ASTR + tok] = xr[i].x;
            As[(dq * 4 + 1) * ASTR + tok] = xr[i].y;
            As[(dq * 4 + 2) * ASTR + tok] = xr[i].z;
            As[(dq * 4 + 3) * ASTR + tok] = xr[i].w;
        }
        {
            int e = tid >> 2, dq = tid & 3;
            Ws[(dq * 4 + 0) * WSTR + e] = wr.x;
            Ws[(dq * 4 + 1) * WSTR + e] = wr.y;
            Ws[(dq * 4 + 2) * WSTR + e] = wr.z;
            Ws[(dq * 4 + 3) * WSTR + e] = wr.w;
        }
        __syncthreads();

        // ---- prefetch next chunk while computing this one ----
        int kn = k0 + BK;
        if (kn < DIM) {
            #pragma unroll
            for (int i = 0; i < 2; i++) {
                int li = i * THREADS + tid; int tok = li >> 2, dq = li & 3;
                xr[i] = *reinterpret_cast<const float4*>(xg + (size_t)tok * DIM + kn + dq * 4);
            }
            {
                int e = tid >> 2, dq = tid & 3;
                wr = *reinterpret_cast<const float4*>(w + (size_t)e * DIM + kn + dq * 4);
            }
        }

        // ---- compute: 16 k-steps x (4 tokens x 4 expert-pairs) FFMA2 ----
        #pragma unroll
        for (int kk = 0; kk < BK; kk++) {
            float4 xf = *reinterpret_cast<const float4*>(&As[kk * ASTR + ty * 4]);
            ulonglong2 w01 = *reinterpret_cast<const ulonglong2*>(&Ws[kk * WSTR + tx * 8]);
            ulonglong2 w23 = *reinterpret_cast<const ulonglong2*>(&Ws[kk * WSTR + tx * 8 + 4]);
            ull wv[4] = { w01.x, w01.y, w23.x, w23.y };
            ull xd[4] = { dup2(xf.x), dup2(xf.y), dup2(xf.z), dup2(xf.w) };
            #pragma unroll
            for (int t = 0; t < 4; t++)
                #pragma unroll
                for (int ep = 0; ep < 4; ep++)
                    acc[t][ep] = fma2(xd[t], wv[ep], acc[t][ep]);
        }
        __syncthreads();
    }

    // ---- dump logits to shared: 8B stores, conflict-light, one-time ----
    #pragma unroll
    for (int t = 0; t < 4; t++)
        #pragma unroll
        for (int ep = 0; ep < 4; ep++)
            *reinterpret_cast<ull*>(&sLog[(ty * 4 + t) * LSTR + tx * 8 + ep * 2]) = acc[t][ep];
    __syncthreads();

    // ---- fused epilogue: 1 thread = 1 token. softmax, +bias select, top-6 ----
    if (tid < BM) {
        float* row = sLog + tid * LSTR;

        float m = row[0];
        #pragma unroll
        for (int e = 1; e < NE; e++) m = fmaxf(m, row[e]);

        float s = 0.f;
        #pragma unroll
        for (int e = 0; e < NE; e++) { float ex = __expf(row[e] - m); row[e] = ex; s += ex; }
        float inv = 1.0f / s;
        #pragma unroll
        for (int e = 0; e < NE; e++) row[e] *= inv;   // original softmax scores

        const int t = block_m + tid;
        float* outw = out + (size_t)t * TOPK;
        float* outi = out + (size_t)TOKENS * TOPK + (size_t)t * TOPK;

        #pragma unroll
        for (int k = 0; k < TOPK; k++) {
            float best = -CUDART_INF_F; int bi = 0;
            #pragma unroll
            for (int e = 0; e < NE; e++) {
                float b = row[e] + sBias[e];   // bias affects selection only
                if (b > best) { best = b; bi = e; }
            }
            outw[k] = row[bi];                 // ROUTE_SCALE == 1.0
            outi[k] = (float)bi;
            row[bi] = -CUDART_INF_F;
        }
    }
}

extern "C" void kernel_launch(void* const* d_in, const int* in_sizes, int n_in,
                              void* d_out, int out_size)
{
    const float* x    = (const float*)d_in[0];
    const float* w    = (const float*)d_in[1];
    const float* bias = (const float*)d_in[2];
    float* out = (float*)d_out;
    gate_kernel<<<TOKENS / BM, THREADS>>>(x, w, bias, out);
}